// round 1
// baseline (speedup 1.0000x reference)
#include <cuda_runtime.h>
#include <math.h>

// Problem constants
#define NN 100000   // nodes
#define FF 256      // feature dim
#define DD 128      // latent dim
#define MM 10       // categories
#define BB 32768    // batch
#define KK 32       // neighbors per node

// ---------------------------------------------------------------------------
// Scratch (static __device__ arrays; allocation is forbidden)
// ---------------------------------------------------------------------------
__device__ float g_flow[NN * DD];    // flow_emb, later overwritten by flow_all
__device__ float g_ce[MM * DD];      // character_emb
__device__ float g_lat[2 * MM * DD]; // lat table for 20 (cat, pa) combos
__device__ float g_wsum[DD * DD];    // linear1_w[:D] + linear1_w[D:]
__device__ float g_agg[BB * DD];     // attention-aggregated rows

// ---------------------------------------------------------------------------
// Kernel 0: zero g_ce (re-run every launch; graph-captured)
// ---------------------------------------------------------------------------
__global__ void k_zero_ce() {
    int i = blockIdx.x * blockDim.x + threadIdx.x;
    if (i < MM * DD) g_ce[i] = 0.0f;
}

// ---------------------------------------------------------------------------
// Kernel 1: flow_emb = feature @ weight_emb + bias   [N,256]x[256,128]
// Tiled fp32 GEMM. BM=64, BN=128(full), BK=32, 256 threads, 8x4 micro-tile.
// ---------------------------------------------------------------------------
__global__ __launch_bounds__(256) void k_gemm_emb(
    const float* __restrict__ feature,
    const float* __restrict__ w_emb,
    const float* __restrict__ b_emb)
{
    __shared__ float As[64 * 32];   // 8 KB
    __shared__ float Bs[32 * 128];  // 16 KB

    const int tid = threadIdx.x;
    const int tx  = tid & 31;       // col group (4 cols)
    const int ty  = tid >> 5;       // row group (8 rows)
    const int row0 = blockIdx.x * 64;

    float4 acc[8];
#pragma unroll
    for (int r = 0; r < 8; ++r) acc[r] = make_float4(0.f, 0.f, 0.f, 0.f);

    for (int k0 = 0; k0 < FF; k0 += 32) {
        // Stage A tile: 64x32 = 512 float4, 2 per thread
#pragma unroll
        for (int i = 0; i < 2; ++i) {
            int fi   = tid + i * 256;
            int arow = fi >> 3;
            int acol = (fi & 7) * 4;
            float4 v = make_float4(0.f, 0.f, 0.f, 0.f);
            if (row0 + arow < NN)
                v = *(const float4*)&feature[(size_t)(row0 + arow) * FF + k0 + acol];
            ((float4*)As)[fi] = v;
        }
        // Stage W tile: 32x128 = 1024 float4, 4 per thread
#pragma unroll
        for (int i = 0; i < 4; ++i) {
            int fi   = tid + i * 256;
            int wrow = fi >> 5;
            int wc4  = fi & 31;
            ((float4*)Bs)[fi] = *(const float4*)&w_emb[(k0 + wrow) * DD + wc4 * 4];
        }
        __syncthreads();

#pragma unroll
        for (int k = 0; k < 32; ++k) {
            float4 b4 = ((const float4*)Bs)[k * 32 + tx];
            float ar[8];
#pragma unroll
            for (int r = 0; r < 8; ++r) ar[r] = As[(ty * 8 + r) * 32 + k];
#pragma unroll
            for (int r = 0; r < 8; ++r) {
                acc[r].x += ar[r] * b4.x;
                acc[r].y += ar[r] * b4.y;
                acc[r].z += ar[r] * b4.z;
                acc[r].w += ar[r] * b4.w;
            }
        }
        __syncthreads();
    }

    float4 bias = ((const float4*)b_emb)[tx];
#pragma unroll
    for (int r = 0; r < 8; ++r) {
        int row = row0 + ty * 8 + r;
        if (row < NN) {
            float4 o = make_float4(acc[r].x + bias.x, acc[r].y + bias.y,
                                   acc[r].z + bias.z, acc[r].w + bias.w);
            *(float4*)&g_flow[(size_t)row * DD + tx * 4] = o;
        }
    }
}

// ---------------------------------------------------------------------------
// Kernel 2: character_emb = flow_char_adj @ flow_emb   [10,N]x[N,128]
// Each block handles a 512-node chunk; thread = output dim d; atomicAdd merge.
// ---------------------------------------------------------------------------
#define CE_CHUNK 512
__global__ __launch_bounds__(128) void k_spmm_ce(const float* __restrict__ adj) {
    __shared__ float adjs[MM][CE_CHUNK];  // 20 KB
    const int d  = threadIdx.x;
    const int n0 = blockIdx.x * CE_CHUNK;
    const int cnt = min(CE_CHUNK, NN - n0);

    for (int m = 0; m < MM; ++m)
        for (int i = d; i < cnt; i += 128)
            adjs[m][i] = adj[(size_t)m * NN + n0 + i];
    __syncthreads();

    float acc[MM];
#pragma unroll
    for (int m = 0; m < MM; ++m) acc[m] = 0.f;

    for (int i = 0; i < cnt; ++i) {
        float fe = g_flow[(size_t)(n0 + i) * DD + d];
#pragma unroll
        for (int m = 0; m < MM; ++m) acc[m] += adjs[m][i] * fe;
    }
#pragma unroll
    for (int m = 0; m < MM; ++m) atomicAdd(&g_ce[m * DD + d], acc[m]);
}

// ---------------------------------------------------------------------------
// Kernel 3: lat table for all 20 (cat, pa) combos.
// lat = sigmoid([ce[cat], ce[pa]] @ weight_character)
// ---------------------------------------------------------------------------
__global__ __launch_bounds__(128) void k_lat(const float* __restrict__ wchar) {
    __shared__ float cc[DD], cp[DD];
    const int combo = blockIdx.x;         // 0..19
    const int c = combo / MM;             // 0..1
    const int p = combo % MM;             // 0..9
    const int d = threadIdx.x;

    cc[d] = g_ce[c * DD + d];
    cp[d] = g_ce[p * DD + d];
    __syncthreads();

    float s = 0.f;
#pragma unroll 4
    for (int e = 0; e < DD; ++e) s += cc[e] * wchar[e * DD + d];
#pragma unroll 4
    for (int e = 0; e < DD; ++e) s += cp[e] * wchar[(DD + e) * DD + d];
    g_lat[combo * DD + d] = 1.0f / (1.0f + expf(-s));
}

// ---------------------------------------------------------------------------
// Kernel 4: Wsum = linear1_w[:D] + linear1_w[D:]  (folds the [agg,agg] concat)
// ---------------------------------------------------------------------------
__global__ void k_wsum(const float* __restrict__ l1w) {
    int i = blockIdx.x * blockDim.x + threadIdx.x;
    if (i < DD * DD) g_wsum[i] = l1w[i] + l1w[DD * DD + i];
}

// ---------------------------------------------------------------------------
// Kernel 5: flow_all = 0.5*(flow_emb + adj0[n]*ce0 + adj1[n]*ce1)  (in place)
// ---------------------------------------------------------------------------
__global__ __launch_bounds__(256) void k_flow_all(const float* __restrict__ adj) {
    int idx = blockIdx.x * blockDim.x + threadIdx.x;  // float4 index
    if (idx >= NN * (DD / 4)) return;
    int n = idx >> 5;           // 32 float4 per row
    int q = idx & 31;

    float a0 = adj[n];
    float a1 = adj[NN + n];
    float4 c0 = ((const float4*)g_ce)[q];          // ce row 0
    float4 c1 = ((const float4*)g_ce)[32 + q];     // ce row 1
    float4 fe = ((const float4*)g_flow)[idx];

    float4 o;
    o.x = 0.5f * (fe.x + a0 * c0.x + a1 * c1.x);
    o.y = 0.5f * (fe.y + a0 * c0.y + a1 * c1.y);
    o.z = 0.5f * (fe.z + a0 * c0.z + a1 * c1.z);
    o.w = 0.5f * (fe.w + a0 * c0.w + a1 * c1.w);
    ((float4*)g_flow)[idx] = o;
}

// ---------------------------------------------------------------------------
// Kernel 6: per-row neighbor attention, single-pass online softmax.
// One warp per batch row; each neighbor row loaded exactly once.
// ---------------------------------------------------------------------------
__global__ __launch_bounds__(256) void k_attn(
    const int* __restrict__ history,
    const float* __restrict__ att_w,
    const float* __restrict__ att_b)
{
    const int lane = threadIdx.x & 31;
    const int warp = threadIdx.x >> 5;
    const int b = blockIdx.x * 8 + warp;

    const int myn = history[(size_t)b * KK + lane];   // one coalesced load
    const float4 aw = ((const float4*)att_w)[lane];
    const float ab = att_b[0];

    float m = -INFINITY, l = 0.f;
    float4 acc = make_float4(0.f, 0.f, 0.f, 0.f);

#pragma unroll 4
    for (int k = 0; k < KK; ++k) {
        int n = __shfl_sync(0xFFFFFFFFu, myn, k);
        float4 v = *(const float4*)&g_flow[(size_t)n * DD + lane * 4];
        float p = v.x * aw.x + v.y * aw.y + v.z * aw.z + v.w * aw.w;
#pragma unroll
        for (int off = 16; off > 0; off >>= 1)
            p += __shfl_xor_sync(0xFFFFFFFFu, p, off);
        float s = p + ab;
        float mn = fmaxf(m, s);
        float corr = __expf(m - mn);     // exp(-inf)=0 on first iter
        float w = __expf(s - mn);
        l = l * corr + w;
        acc.x = acc.x * corr + w * v.x;
        acc.y = acc.y * corr + w * v.y;
        acc.z = acc.z * corr + w * v.z;
        acc.w = acc.w * corr + w * v.w;
        m = mn;
    }
    float inv = 1.0f / l;
    float4 o = make_float4(acc.x * inv, acc.y * inv, acc.z * inv, acc.w * inv);
    *(float4*)&g_agg[(size_t)b * DD + lane * 4] = o;
}

// ---------------------------------------------------------------------------
// Kernel 7: out = relu(agg @ Wsum + b1);  pred_r/n = dot(lat[combo], out)
// One warp per batch row.
// ---------------------------------------------------------------------------
__global__ __launch_bounds__(256) void k_final(
    const float* __restrict__ l1b,
    const int* __restrict__ cat_r,
    const int* __restrict__ cat_n,
    const int* __restrict__ pa,
    float* __restrict__ out)
{
    __shared__ float sh[8][DD];
    const int lane = threadIdx.x & 31;
    const int warp = threadIdx.x >> 5;
    const int b = blockIdx.x * 8 + warp;

    // stage agg row
    float4 a4 = *(const float4*)&g_agg[(size_t)b * DD + lane * 4];
    *(float4*)&sh[warp][lane * 4] = a4;
    __syncwarp();

    float4 acc = make_float4(0.f, 0.f, 0.f, 0.f);
    const float4* W4 = (const float4*)g_wsum;
#pragma unroll 4
    for (int e = 0; e < DD; ++e) {
        float a = sh[warp][e];
        float4 w = W4[e * 32 + lane];
        acc.x += a * w.x; acc.y += a * w.y;
        acc.z += a * w.z; acc.w += a * w.w;
    }
    float4 bias = ((const float4*)l1b)[lane];
    float4 o;
    o.x = fmaxf(acc.x + bias.x, 0.f);
    o.y = fmaxf(acc.y + bias.y, 0.f);
    o.z = fmaxf(acc.z + bias.z, 0.f);
    o.w = fmaxf(acc.w + bias.w, 0.f);

    int pav = pa[b];
    int ir = cat_r[b] * MM + pav;
    int in_ = cat_n[b] * MM + pav;
    float4 lr = ((const float4*)g_lat)[ir * 32 + lane];
    float4 ln = ((const float4*)g_lat)[in_ * 32 + lane];

    float pr = o.x * lr.x + o.y * lr.y + o.z * lr.z + o.w * lr.w;
    float pn = o.x * ln.x + o.y * ln.y + o.z * ln.z + o.w * ln.w;
#pragma unroll
    for (int off = 16; off > 0; off >>= 1) {
        pr += __shfl_xor_sync(0xFFFFFFFFu, pr, off);
        pn += __shfl_xor_sync(0xFFFFFFFFu, pn, off);
    }
    if (lane == 0) {
        out[b] = pr;
        out[BB + b] = pn;
    }
}

// ---------------------------------------------------------------------------
// Launch (graph-capturable: kernel launches only, single stream)
// Input order (metadata / setup_inputs dict order):
//  0 feature[N,F] 1 flow_char_adj[M,N] 2 history[B,K] 3 item_id[B]
//  4 category_r[B] 5 category_n[B] 6 PA_level[B]
//  7 weight_emb[F,D] 8 bias_emb[D] 9 weight_character[2D,D]
// 10 att1_w[D,1] 11 att1_b[1] 12 linear1_w[2D,D] 13 linear1_b[D]
// Output: [pred_r (B) | pred_n (B)]
// ---------------------------------------------------------------------------
extern "C" void kernel_launch(void* const* d_in, const int* in_sizes, int n_in,
                              void* d_out, int out_size)
{
    const float* feature = (const float*)d_in[0];
    const float* adj     = (const float*)d_in[1];
    const int*   history = (const int*)d_in[2];
    const int*   cat_r   = (const int*)d_in[4];
    const int*   cat_n   = (const int*)d_in[5];
    const int*   pa      = (const int*)d_in[6];
    const float* w_emb   = (const float*)d_in[7];
    const float* b_emb   = (const float*)d_in[8];
    const float* wchar   = (const float*)d_in[9];
    const float* att_w   = (const float*)d_in[10];
    const float* att_b   = (const float*)d_in[11];
    const float* l1w     = (const float*)d_in[12];
    const float* l1b     = (const float*)d_in[13];
    float* out = (float*)d_out;

    k_zero_ce<<<(MM * DD + 127) / 128, 128>>>();
    k_gemm_emb<<<(NN + 63) / 64, 256>>>(feature, w_emb, b_emb);
    k_spmm_ce<<<(NN + CE_CHUNK - 1) / CE_CHUNK, 128>>>(adj);
    k_lat<<<2 * MM, 128>>>(wchar);
    k_wsum<<<(DD * DD + 255) / 256, 256>>>(l1w);
    k_flow_all<<<(NN * (DD / 4) + 255) / 256, 256>>>(adj);
    k_attn<<<BB / 8, 256>>>(history, att_w, att_b);
    k_final<<<BB / 8, 256>>>(l1b, cat_r, cat_n, pa, out);
}

// round 2
// speedup vs baseline: 1.1798x; 1.1798x over previous
#include <cuda_runtime.h>
#include <math.h>

// Problem constants
#define NN 100000   // nodes
#define FF 256      // feature dim
#define DD 128      // latent dim
#define MM 10       // categories
#define BB 32768    // batch
#define KK 32       // neighbors per node

// ---------------------------------------------------------------------------
// Scratch (static __device__ arrays; allocation is forbidden)
// ---------------------------------------------------------------------------
__device__ float g_flow[NN * DD];    // flow_emb, later overwritten by flow_all
__device__ float g_ce[MM * DD];      // character_emb
__device__ float g_uv[12 * DD];      // u[2][D] then v[10][D]
__device__ float g_lat[2 * MM * DD]; // lat table for 20 (cat, pa) combos
__device__ float g_wsum[DD * DD];    // linear1_w[:D] + linear1_w[D:]
__device__ float g_agg[BB * DD];     // attention-aggregated rows
__device__ float g_out[BB * DD];     // relu(agg @ Wsum + b)

// ---------------------------------------------------------------------------
// TF32 helpers (3xTF32 split: a = hi + lo, fp32-class accuracy on tensor cores)
// ---------------------------------------------------------------------------
__device__ __forceinline__ unsigned f2tf(float x) {
    unsigned r;
    asm("cvt.rna.tf32.f32 %0, %1;" : "=r"(r) : "f"(x));
    return r;
}
__device__ __forceinline__ void mma_tf32(
    float& c0, float& c1, float& c2, float& c3,
    unsigned a0, unsigned a1, unsigned a2, unsigned a3,
    unsigned b0, unsigned b1)
{
    asm volatile(
        "mma.sync.aligned.m16n8k8.row.col.f32.tf32.tf32.f32 "
        "{%0,%1,%2,%3},{%4,%5,%6,%7},{%8,%9},{%0,%1,%2,%3};"
        : "+f"(c0), "+f"(c1), "+f"(c2), "+f"(c3)
        : "r"(a0), "r"(a1), "r"(a2), "r"(a3), "r"(b0), "r"(b1));
}

// ---------------------------------------------------------------------------
// Unified mma GEMM:  C[M,128] = op(A[M,K] @ B[K,128] + bias), op = relu?
// BM=64, BN=128(full), BK=32; 256 threads = 8 warps (4x2); warp tile 16x64.
// 3xTF32: D += Ahi*Blo + Alo*Bhi + Ahi*Bhi
// ---------------------------------------------------------------------------
#define AS_LD 36
#define BS_LD 136
__global__ __launch_bounds__(256) void k_mma_gemm(
    const float* __restrict__ A,
    const float* __restrict__ B,
    const float* __restrict__ bias,
    float* __restrict__ C,
    int Mrows, int Kdim, int relu)
{
    __shared__ __align__(16) float As[64 * AS_LD];
    __shared__ __align__(16) float Bs[32 * BS_LD];

    const int tid    = threadIdx.x;
    const int lane   = tid & 31;
    const int warp   = tid >> 5;
    const int warp_m = warp >> 1;       // 0..3 (16 rows each)
    const int warp_n = warp & 1;        // 0..1 (64 cols each)
    const int row0   = blockIdx.x * 64;
    const int lg     = lane >> 2;       // 0..7
    const int lk     = lane & 3;        // 0..3

    float c[8][4];
#pragma unroll
    for (int t = 0; t < 8; ++t)
#pragma unroll
        for (int i = 0; i < 4; ++i) c[t][i] = 0.f;

    const int kt_iters = Kdim >> 5;     // K/32

    // --- prefetch tile 0 into registers ---
    float4 ra[2], rb[4];
#pragma unroll
    for (int i = 0; i < 2; ++i) {
        int fi = tid + i * 256;
        int arow = fi >> 3, ac4 = fi & 7;
        ra[i] = make_float4(0.f, 0.f, 0.f, 0.f);
        if (row0 + arow < Mrows)
            ra[i] = *(const float4*)&A[(size_t)(row0 + arow) * Kdim + ac4 * 4];
    }
#pragma unroll
    for (int i = 0; i < 4; ++i) {
        int fi = tid + i * 256;
        int brow = fi >> 5, bc4 = fi & 31;
        rb[i] = *(const float4*)&B[(size_t)brow * DD + bc4 * 4];
    }

    for (int kt = 0; kt < kt_iters; ++kt) {
        // store staged regs into smem
#pragma unroll
        for (int i = 0; i < 2; ++i) {
            int fi = tid + i * 256;
            int arow = fi >> 3, ac4 = fi & 7;
            *(float4*)&As[arow * AS_LD + ac4 * 4] = ra[i];
        }
#pragma unroll
        for (int i = 0; i < 4; ++i) {
            int fi = tid + i * 256;
            int brow = fi >> 5, bc4 = fi & 31;
            *(float4*)&Bs[brow * BS_LD + bc4 * 4] = rb[i];
        }
        __syncthreads();

        // prefetch next tile
        if (kt + 1 < kt_iters) {
            int k0 = (kt + 1) * 32;
#pragma unroll
            for (int i = 0; i < 2; ++i) {
                int fi = tid + i * 256;
                int arow = fi >> 3, ac4 = fi & 7;
                ra[i] = make_float4(0.f, 0.f, 0.f, 0.f);
                if (row0 + arow < Mrows)
                    ra[i] = *(const float4*)&A[(size_t)(row0 + arow) * Kdim + k0 + ac4 * 4];
            }
#pragma unroll
            for (int i = 0; i < 4; ++i) {
                int fi = tid + i * 256;
                int brow = fi >> 5, bc4 = fi & 31;
                rb[i] = *(const float4*)&B[(size_t)(k0 + brow) * DD + bc4 * 4];
            }
        }

        // compute: 4 k8-steps
#pragma unroll
        for (int ks = 0; ks < 4; ++ks) {
            const int kc = ks * 8 + lk;
            float a0 = As[(warp_m * 16 + lg) * AS_LD + kc];
            float a1 = As[(warp_m * 16 + 8 + lg) * AS_LD + kc];
            float a2 = As[(warp_m * 16 + lg) * AS_LD + kc + 4];
            float a3 = As[(warp_m * 16 + 8 + lg) * AS_LD + kc + 4];
            unsigned ah0 = f2tf(a0), ah1 = f2tf(a1), ah2 = f2tf(a2), ah3 = f2tf(a3);
            unsigned al0 = f2tf(a0 - __uint_as_float(ah0));
            unsigned al1 = f2tf(a1 - __uint_as_float(ah1));
            unsigned al2 = f2tf(a2 - __uint_as_float(ah2));
            unsigned al3 = f2tf(a3 - __uint_as_float(ah3));

#pragma unroll
            for (int nt = 0; nt < 8; ++nt) {
                int coln = warp_n * 64 + nt * 8 + lg;
                float b0 = Bs[(ks * 8 + lk) * BS_LD + coln];
                float b1 = Bs[(ks * 8 + lk + 4) * BS_LD + coln];
                unsigned bh0 = f2tf(b0), bh1 = f2tf(b1);
                unsigned bl0 = f2tf(b0 - __uint_as_float(bh0));
                unsigned bl1 = f2tf(b1 - __uint_as_float(bh1));
                // small cross terms first, big term last
                mma_tf32(c[nt][0], c[nt][1], c[nt][2], c[nt][3],
                         ah0, ah1, ah2, ah3, bl0, bl1);
                mma_tf32(c[nt][0], c[nt][1], c[nt][2], c[nt][3],
                         al0, al1, al2, al3, bh0, bh1);
                mma_tf32(c[nt][0], c[nt][1], c[nt][2], c[nt][3],
                         ah0, ah1, ah2, ah3, bh0, bh1);
            }
        }
        __syncthreads();
    }

    // epilogue
    const int r0 = row0 + warp_m * 16 + lg;
    const int r1 = r0 + 8;
#pragma unroll
    for (int nt = 0; nt < 8; ++nt) {
        int cb = warp_n * 64 + nt * 8 + 2 * lk;
        float bx = bias[cb], by = bias[cb + 1];
        float2 v0 = make_float2(c[nt][0] + bx, c[nt][1] + by);
        float2 v1 = make_float2(c[nt][2] + bx, c[nt][3] + by);
        if (relu) {
            v0.x = fmaxf(v0.x, 0.f); v0.y = fmaxf(v0.y, 0.f);
            v1.x = fmaxf(v1.x, 0.f); v1.y = fmaxf(v1.y, 0.f);
        }
        if (r0 < Mrows) *(float2*)&C[(size_t)r0 * DD + cb] = v0;
        if (r1 < Mrows) *(float2*)&C[(size_t)r1 * DD + cb] = v1;
    }
}

// ---------------------------------------------------------------------------
// Kernel 0: zero g_ce
// ---------------------------------------------------------------------------
__global__ void k_zero_ce() {
    int i = blockIdx.x * blockDim.x + threadIdx.x;
    if (i < MM * DD) g_ce[i] = 0.0f;
}

// ---------------------------------------------------------------------------
// character_emb = flow_char_adj @ flow_emb   [10,N]x[N,128]
// ---------------------------------------------------------------------------
#define CE_CHUNK 512
__global__ __launch_bounds__(128) void k_spmm_ce(const float* __restrict__ adj) {
    __shared__ float adjs[MM][CE_CHUNK];
    const int d  = threadIdx.x;
    const int n0 = blockIdx.x * CE_CHUNK;
    const int cnt = min(CE_CHUNK, NN - n0);

    for (int m = 0; m < MM; ++m)
        for (int i = d; i < cnt; i += 128)
            adjs[m][i] = adj[(size_t)m * NN + n0 + i];
    __syncthreads();

    float acc[MM];
#pragma unroll
    for (int m = 0; m < MM; ++m) acc[m] = 0.f;

#pragma unroll 4
    for (int i = 0; i < cnt; ++i) {
        float fe = g_flow[(size_t)(n0 + i) * DD + d];
#pragma unroll
        for (int m = 0; m < MM; ++m) acc[m] += adjs[m][i] * fe;
    }
#pragma unroll
    for (int m = 0; m < MM; ++m) atomicAdd(&g_ce[m * DD + d], acc[m]);
}

// ---------------------------------------------------------------------------
// u[c][d] = dot(ce[c], W_low[:,d]) (c=0,1); v[p][d] = dot(ce[p], W_high[:,d])
// grid 12 blocks x 128 threads; fully parallel, coalesced W reads.
// ---------------------------------------------------------------------------
__global__ __launch_bounds__(128) void k_uv(const float* __restrict__ wchar) {
    __shared__ float coef[DD];
    const int j = blockIdx.x;                 // 0,1 -> u; 2..11 -> v
    const int d = threadIdx.x;
    const int src = (j < 2) ? j : (j - 2);
    const int off = (j < 2) ? 0 : DD;

    coef[d] = g_ce[src * DD + d];
    __syncthreads();

    float s = 0.f;
#pragma unroll 8
    for (int e = 0; e < DD; ++e)
        s += coef[e] * wchar[(size_t)(off + e) * DD + d];
    g_uv[j * DD + d] = s;
}

// ---------------------------------------------------------------------------
// lat[combo][d] = sigmoid(u[c][d] + v[p][d]), combo = c*10 + p
// ---------------------------------------------------------------------------
__global__ void k_lat_combine() {
    int idx = blockIdx.x * blockDim.x + threadIdx.x;
    if (idx >= 2 * MM * DD) return;
    int combo = idx >> 7;
    int d = idx & 127;
    int cc = combo / MM;
    int p = combo % MM;
    float s = g_uv[cc * DD + d] + g_uv[(2 + p) * DD + d];
    g_lat[idx] = 1.0f / (1.0f + expf(-s));
}

// ---------------------------------------------------------------------------
// Wsum = linear1_w[:D] + linear1_w[D:]
// ---------------------------------------------------------------------------
__global__ void k_wsum(const float* __restrict__ l1w) {
    int i = blockIdx.x * blockDim.x + threadIdx.x;
    if (i < DD * DD) g_wsum[i] = l1w[i] + l1w[DD * DD + i];
}

// ---------------------------------------------------------------------------
// flow_all = 0.5*(flow_emb + adj0[n]*ce0 + adj1[n]*ce1)  (in place)
// ---------------------------------------------------------------------------
__global__ __launch_bounds__(256) void k_flow_all(const float* __restrict__ adj) {
    int idx = blockIdx.x * blockDim.x + threadIdx.x;  // float4 index
    if (idx >= NN * (DD / 4)) return;
    int n = idx >> 5;
    int q = idx & 31;

    float a0 = adj[n];
    float a1 = adj[NN + n];
    float4 c0 = ((const float4*)g_ce)[q];
    float4 c1 = ((const float4*)g_ce)[32 + q];
    float4 fe = ((const float4*)g_flow)[idx];

    float4 o;
    o.x = 0.5f * (fe.x + a0 * c0.x + a1 * c1.x);
    o.y = 0.5f * (fe.y + a0 * c0.y + a1 * c1.y);
    o.z = 0.5f * (fe.z + a0 * c0.z + a1 * c1.z);
    o.w = 0.5f * (fe.w + a0 * c0.w + a1 * c1.w);
    ((float4*)g_flow)[idx] = o;
}

// ---------------------------------------------------------------------------
// per-row neighbor attention, single-pass online softmax; warp per row
// ---------------------------------------------------------------------------
__global__ __launch_bounds__(256) void k_attn(
    const int* __restrict__ history,
    const float* __restrict__ att_w,
    const float* __restrict__ att_b)
{
    const int lane = threadIdx.x & 31;
    const int warp = threadIdx.x >> 5;
    const int b = blockIdx.x * 8 + warp;

    const int myn = history[(size_t)b * KK + lane];
    const float4 aw = ((const float4*)att_w)[lane];
    const float ab = att_b[0];

    float m = -INFINITY, l = 0.f;
    float4 acc = make_float4(0.f, 0.f, 0.f, 0.f);

#pragma unroll 4
    for (int k = 0; k < KK; ++k) {
        int n = __shfl_sync(0xFFFFFFFFu, myn, k);
        float4 v = *(const float4*)&g_flow[(size_t)n * DD + lane * 4];
        float p = v.x * aw.x + v.y * aw.y + v.z * aw.z + v.w * aw.w;
#pragma unroll
        for (int off = 16; off > 0; off >>= 1)
            p += __shfl_xor_sync(0xFFFFFFFFu, p, off);
        float s = p + ab;
        float mn = fmaxf(m, s);
        float corr = __expf(m - mn);
        float w = __expf(s - mn);
        l = l * corr + w;
        acc.x = acc.x * corr + w * v.x;
        acc.y = acc.y * corr + w * v.y;
        acc.z = acc.z * corr + w * v.z;
        acc.w = acc.w * corr + w * v.w;
        m = mn;
    }
    float inv = 1.0f / l;
    float4 o = make_float4(acc.x * inv, acc.y * inv, acc.z * inv, acc.w * inv);
    *(float4*)&g_agg[(size_t)b * DD + lane * 4] = o;
}

// ---------------------------------------------------------------------------
// pred: pr/pn = dot(lat[combo], out_row);  warp per row
// ---------------------------------------------------------------------------
__global__ __launch_bounds__(256) void k_pred(
    const int* __restrict__ cat_r,
    const int* __restrict__ cat_n,
    const int* __restrict__ pa,
    float* __restrict__ out)
{
    const int lane = threadIdx.x & 31;
    const int warp = threadIdx.x >> 5;
    const int b = blockIdx.x * 8 + warp;

    float4 o = *(const float4*)&g_out[(size_t)b * DD + lane * 4];

    int pav = pa[b];
    int ir  = cat_r[b] * MM + pav;
    int in_ = cat_n[b] * MM + pav;
    float4 lr = ((const float4*)g_lat)[ir * 32 + lane];
    float4 ln = ((const float4*)g_lat)[in_ * 32 + lane];

    float pr = o.x * lr.x + o.y * lr.y + o.z * lr.z + o.w * lr.w;
    float pn = o.x * ln.x + o.y * ln.y + o.z * ln.z + o.w * ln.w;
#pragma unroll
    for (int off = 16; off > 0; off >>= 1) {
        pr += __shfl_xor_sync(0xFFFFFFFFu, pr, off);
        pn += __shfl_xor_sync(0xFFFFFFFFu, pn, off);
    }
    if (lane == 0) {
        out[b] = pr;
        out[BB + b] = pn;
    }
}

// ---------------------------------------------------------------------------
// Launch. Input order:
//  0 feature 1 flow_char_adj 2 history 3 item_id 4 category_r 5 category_n
//  6 PA_level 7 weight_emb 8 bias_emb 9 weight_character 10 att1_w 11 att1_b
// 12 linear1_w 13 linear1_b ; out = [pred_r | pred_n]
// ---------------------------------------------------------------------------
extern "C" void kernel_launch(void* const* d_in, const int* in_sizes, int n_in,
                              void* d_out, int out_size)
{
    const float* feature = (const float*)d_in[0];
    const float* adj     = (const float*)d_in[1];
    const int*   history = (const int*)d_in[2];
    const int*   cat_r   = (const int*)d_in[4];
    const int*   cat_n   = (const int*)d_in[5];
    const int*   pa      = (const int*)d_in[6];
    const float* w_emb   = (const float*)d_in[7];
    const float* b_emb   = (const float*)d_in[8];
    const float* wchar   = (const float*)d_in[9];
    const float* att_w   = (const float*)d_in[10];
    const float* att_b   = (const float*)d_in[11];
    const float* l1w     = (const float*)d_in[12];
    const float* l1b     = (const float*)d_in[13];
    float* out = (float*)d_out;

    float* flow;  cudaGetSymbolAddress((void**)&flow,  g_flow);
    float* aggp;  cudaGetSymbolAddress((void**)&aggp,  g_agg);
    float* outp;  cudaGetSymbolAddress((void**)&outp,  g_out);
    float* wsump; cudaGetSymbolAddress((void**)&wsump, g_wsum);

    k_zero_ce<<<(MM * DD + 127) / 128, 128>>>();
    k_mma_gemm<<<(NN + 63) / 64, 256>>>(feature, w_emb, b_emb, flow, NN, FF, 0);
    k_spmm_ce<<<(NN + CE_CHUNK - 1) / CE_CHUNK, 128>>>(adj);
    k_uv<<<12, 128>>>(wchar);
    k_lat_combine<<<(2 * MM * DD + 255) / 256, 256>>>();
    k_wsum<<<(DD * DD + 255) / 256, 256>>>(l1w);
    k_flow_all<<<(NN * (DD / 4) + 255) / 256, 256>>>(adj);
    k_attn<<<BB / 8, 256>>>(history, att_w, att_b);
    k_mma_gemm<<<(BB + 63) / 64, 256>>>(aggp, wsump, l1b, outp, BB, DD, 1);
    k_pred<<<BB / 8, 256>>>(cat_r, cat_n, pa, out);
}

// round 7
// speedup vs baseline: 1.9162x; 1.6242x over previous
#include <cuda_runtime.h>
#include <cuda_fp16.h>
#include <math.h>

// Problem constants
#define NN 100000   // nodes
#define FF 256      // feature dim
#define DD 128      // latent dim
#define MM 10       // categories
#define BB 32768    // batch
#define KK 32       // neighbors

// ---------------------------------------------------------------------------
// Scratch
// ---------------------------------------------------------------------------
__device__ __half g_flowh[NN * DD];   // flow_emb in fp16 (attn/spmm table)
__device__ float  g_ce[MM * DD];      // character_emb
__device__ float  g_uv[12 * DD];      // u[2][D], v[10][D]
__device__ float  g_lat[2 * MM * DD]; // sigmoid lat table (20 combos)
__device__ float  g_wsum[DD * DD];    // l1w[:D] + l1w[D:]
__device__ float  g_agg[BB * DD];     // attention output

// ---------------------------------------------------------------------------
// bf16 2-way split helpers
// ---------------------------------------------------------------------------
__device__ __forceinline__ unsigned pk2(float lo, float hi) {
    unsigned r;
    asm("cvt.rn.bf16x2.f32 %0, %1, %2;" : "=r"(r) : "f"(hi), "f"(lo));
    return r;
}
// split pair (lo = even-k elem, hi = odd-k elem) into bf16x2 hi-plane + residual lo-plane
__device__ __forceinline__ void cvt_pair(float lo, float hi, unsigned& h, unsigned& l) {
    h = pk2(lo, hi);
    float flo = __uint_as_float(h << 16);
    float fhi = __uint_as_float(h & 0xFFFF0000u);
    l = pk2(lo - flo, hi - fhi);
}
__device__ __forceinline__ void mma_bf16(
    float* c, unsigned a0, unsigned a1, unsigned a2, unsigned a3,
    unsigned b0, unsigned b1)
{
    asm volatile(
        "mma.sync.aligned.m16n8k16.row.col.f32.bf16.bf16.f32 "
        "{%0,%1,%2,%3},{%4,%5,%6,%7},{%8,%9},{%0,%1,%2,%3};"
        : "+f"(c[0]), "+f"(c[1]), "+f"(c[2]), "+f"(c[3])
        : "r"(a0), "r"(a1), "r"(a2), "r"(a3), "r"(b0), "r"(b1));
}

// ---------------------------------------------------------------------------
// Unified bf16-split GEMM: C[M,128] = A[M,K] @ B[K,128] + bias
// BM=128, BN=128, BK=32; 256 threads; warp grid 4(m)x2(n); warp tile m32 n64.
// MODE 0: write C as fp16 to g_flowh.
// MODE 1: fused epilogue: out_row = relu(C+bias); atomicAdd lat-dots into out.
// ---------------------------------------------------------------------------
#define AS_LD 40     // fp32 elements per A row in smem
#define BS2_LD 132   // packed pairs per Bp row

template<int MODE>
__global__ __launch_bounds__(256) void k_gemm(
    const float* __restrict__ A,
    const float* __restrict__ B,
    const float* __restrict__ bias,
    int Mrows, int Kdim,
    const int* __restrict__ cat_r,
    const int* __restrict__ cat_n,
    const int* __restrict__ pa,
    float* __restrict__ out)
{
    __shared__ __align__(16) unsigned char smem_raw[37376];
    float*    As = (float*)smem_raw;                    // 128 x 40 fp32
    unsigned* Bh = (unsigned*)(smem_raw + 20480);       // 16 x 132 packed hi
    unsigned* Bl = (unsigned*)(smem_raw + 28928);       // 16 x 132 packed lo

    const int tid  = threadIdx.x;
    const int lane = tid & 31;
    const int warp = tid >> 5;
    const int wm   = warp >> 1;     // 0..3
    const int wn   = warp & 1;      // 0..1
    const int lg   = lane >> 2;     // 0..7
    const int lk   = lane & 3;      // 0..3
    const int row0 = blockIdx.x * 128;

    float c[2][8][4];
#pragma unroll
    for (int mt = 0; mt < 2; ++mt)
#pragma unroll
        for (int nt = 0; nt < 8; ++nt)
#pragma unroll
            for (int i = 0; i < 4; ++i) c[mt][nt][i] = 0.f;

    const int kt_iters = Kdim >> 5;

    // staged register tiles
    float4 ra[4];         // A: 4 float4/thread (128x32 tile)
    float4 rb0[2], rb1[2];// B: 2 items/thread, each = rows 2k2 and 2k2+1

    // prefetch tile 0
#pragma unroll
    for (int i = 0; i < 4; ++i) {
        int id = tid + i * 256;
        int r = id >> 3, c4 = id & 7;
        ra[i] = make_float4(0.f, 0.f, 0.f, 0.f);
        if (row0 + r < Mrows)
            ra[i] = *(const float4*)&A[(size_t)(row0 + r) * Kdim + c4 * 4];
    }
#pragma unroll
    for (int i = 0; i < 2; ++i) {
        int id = tid + i * 256;
        int k2 = id >> 5, c4 = id & 31;
        rb0[i] = *(const float4*)&B[(size_t)(2 * k2)     * DD + c4 * 4];
        rb1[i] = *(const float4*)&B[(size_t)(2 * k2 + 1) * DD + c4 * 4];
    }

    for (int kt = 0; kt < kt_iters; ++kt) {
        // --- stage to smem (convert B to bf16 hi/lo packed planes) ---
#pragma unroll
        for (int i = 0; i < 4; ++i) {
            int id = tid + i * 256;
            int r = id >> 3, c4 = id & 7;
            *(float4*)&As[r * AS_LD + c4 * 4] = ra[i];
        }
#pragma unroll
        for (int i = 0; i < 2; ++i) {
            int id = tid + i * 256;
            int k2 = id >> 5, c4 = id & 31;
            const float* e0 = (const float*)&rb0[i];
            const float* e1 = (const float*)&rb1[i];
            unsigned hj[4], lj[4];
#pragma unroll
            for (int j = 0; j < 4; ++j) cvt_pair(e0[j], e1[j], hj[j], lj[j]);
            *(uint4*)&Bh[k2 * BS2_LD + c4 * 4] = make_uint4(hj[0], hj[1], hj[2], hj[3]);
            *(uint4*)&Bl[k2 * BS2_LD + c4 * 4] = make_uint4(lj[0], lj[1], lj[2], lj[3]);
        }
        __syncthreads();

        // --- prefetch next tile ---
        if (kt + 1 < kt_iters) {
            int k0 = (kt + 1) * 32;
#pragma unroll
            for (int i = 0; i < 4; ++i) {
                int id = tid + i * 256;
                int r = id >> 3, c4 = id & 7;
                ra[i] = make_float4(0.f, 0.f, 0.f, 0.f);
                if (row0 + r < Mrows)
                    ra[i] = *(const float4*)&A[(size_t)(row0 + r) * Kdim + k0 + c4 * 4];
            }
#pragma unroll
            for (int i = 0; i < 2; ++i) {
                int id = tid + i * 256;
                int k2 = id >> 5, c4 = id & 31;
                rb0[i] = *(const float4*)&B[(size_t)(k0 + 2 * k2)     * DD + c4 * 4];
                rb1[i] = *(const float4*)&B[(size_t)(k0 + 2 * k2 + 1) * DD + c4 * 4];
            }
        }

        // --- compute: 2 x k16 steps ---
#pragma unroll
        for (int s = 0; s < 2; ++s) {
            unsigned ah[2][4], al[2][4];
#pragma unroll
            for (int mt = 0; mt < 2; ++mt) {
                int r = wm * 32 + mt * 16 + lg;
                int cb = s * 16 + 2 * lk;
                float2 p0 = *(const float2*)&As[r * AS_LD + cb];
                float2 p1 = *(const float2*)&As[(r + 8) * AS_LD + cb];
                float2 p2 = *(const float2*)&As[r * AS_LD + cb + 8];
                float2 p3 = *(const float2*)&As[(r + 8) * AS_LD + cb + 8];
                cvt_pair(p0.x, p0.y, ah[mt][0], al[mt][0]);
                cvt_pair(p1.x, p1.y, ah[mt][1], al[mt][1]);
                cvt_pair(p2.x, p2.y, ah[mt][2], al[mt][2]);
                cvt_pair(p3.x, p3.y, ah[mt][3], al[mt][3]);
            }
#pragma unroll
            for (int nt = 0; nt < 8; ++nt) {
                int col = wn * 64 + nt * 8 + lg;
                unsigned bh0 = Bh[(s * 8 + lk)     * BS2_LD + col];
                unsigned bh1 = Bh[(s * 8 + lk + 4) * BS2_LD + col];
                unsigned bl0 = Bl[(s * 8 + lk)     * BS2_LD + col];
                unsigned bl1 = Bl[(s * 8 + lk + 4) * BS2_LD + col];
#pragma unroll
                for (int mt = 0; mt < 2; ++mt) {
                    mma_bf16(c[mt][nt], ah[mt][0], ah[mt][1], ah[mt][2], ah[mt][3], bl0, bl1);
                    mma_bf16(c[mt][nt], al[mt][0], al[mt][1], al[mt][2], al[mt][3], bh0, bh1);
                    mma_bf16(c[mt][nt], ah[mt][0], ah[mt][1], ah[mt][2], ah[mt][3], bh0, bh1);
                }
            }
        }
        __syncthreads();
    }

    if (MODE == 0) {
        // fp16 store via smem transpose for coalesced uint4 writes
        __half* Hs = (__half*)smem_raw;   // stride 136 halves per row
#pragma unroll
        for (int mt = 0; mt < 2; ++mt)
#pragma unroll
            for (int nt = 0; nt < 8; ++nt) {
                int r = wm * 32 + mt * 16 + lg;
                int col = wn * 64 + nt * 8 + 2 * lk;
                float bx = bias[col], by = bias[col + 1];
                __half2 v0 = __floats2half2_rn(c[mt][nt][0] + bx, c[mt][nt][1] + by);
                __half2 v1 = __floats2half2_rn(c[mt][nt][2] + bx, c[mt][nt][3] + by);
                *(__half2*)&Hs[r * 136 + col] = v0;
                *(__half2*)&Hs[(r + 8) * 136 + col] = v1;
            }
        __syncthreads();
#pragma unroll
        for (int it = 0; it < 8; ++it) {
            int id = tid + it * 256;
            int r = id >> 4, seg = id & 15;
            if (row0 + r < Mrows)
                *(uint4*)&g_flowh[(size_t)(row0 + r) * DD + seg * 8] =
                    *(const uint4*)&Hs[r * 136 + seg * 8];
        }
    } else {
        // fused: o = relu(c+bias); pr/pn = dot(lat, o); atomicAdd into out
#pragma unroll
        for (int mt = 0; mt < 2; ++mt)
#pragma unroll
            for (int h = 0; h < 2; ++h) {
                int b = row0 + wm * 32 + mt * 16 + h * 8 + lg;
                int pav = pa[b];
                int ir  = cat_r[b] * MM + pav;
                int in_ = cat_n[b] * MM + pav;
                const float* latr = &g_lat[ir * DD];
                const float* latn = &g_lat[in_ * DD];
                float pr = 0.f, pn = 0.f;
#pragma unroll
                for (int nt = 0; nt < 8; ++nt) {
                    int col = wn * 64 + nt * 8 + 2 * lk;
                    float o0 = fmaxf(c[mt][nt][h * 2 + 0] + bias[col], 0.f);
                    float o1 = fmaxf(c[mt][nt][h * 2 + 1] + bias[col + 1], 0.f);
                    float2 lr = *(const float2*)&latr[col];
                    float2 ln = *(const float2*)&latn[col];
                    pr += o0 * lr.x + o1 * lr.y;
                    pn += o0 * ln.x + o1 * ln.y;
                }
                pr += __shfl_xor_sync(0xFFFFFFFFu, pr, 1);
                pr += __shfl_xor_sync(0xFFFFFFFFu, pr, 2);
                pn += __shfl_xor_sync(0xFFFFFFFFu, pn, 1);
                pn += __shfl_xor_sync(0xFFFFFFFFu, pn, 2);
                if (lk == 0) {
                    atomicAdd(&out[b], pr);
                    atomicAdd(&out[BB + b], pn);
                }
            }
    }
}

// ---------------------------------------------------------------------------
// prep: zero out + zero ce + wsum
// ---------------------------------------------------------------------------
__global__ void k_prep(const float* __restrict__ l1w, float* __restrict__ out) {
    int i = blockIdx.x * blockDim.x + threadIdx.x;
    if (i < 2 * BB) out[i] = 0.f;
    if (i < MM * DD) g_ce[i] = 0.f;
    if (i < DD * DD) g_wsum[i] = l1w[i] + l1w[DD * DD + i];
}

// ---------------------------------------------------------------------------
// character_emb = adj @ flow_emb   (fp16 table reads, smem half-merge)
// block = 128 nodes; 256 threads = 2 halves x 128 dims
// ---------------------------------------------------------------------------
__global__ __launch_bounds__(256) void k_spmm(const float* __restrict__ adj) {
    __shared__ float adjs[MM][128];
    const int d    = threadIdx.x & 127;
    const int half = threadIdx.x >> 7;
    const int n0   = blockIdx.x * 128;
    const int cnt  = min(128, NN - n0);

    for (int m = half; m < MM; m += 2)
        adjs[m][d] = (d < cnt) ? adj[(size_t)m * NN + n0 + d] : 0.f;
    __syncthreads();

    float acc[MM];
#pragma unroll
    for (int m = 0; m < MM; ++m) acc[m] = 0.f;

    const int i0 = half * 64, i1 = min(half * 64 + 64, cnt);
#pragma unroll 4
    for (int i = i0; i < i1; ++i) {
        float fe = __half2float(g_flowh[(size_t)(n0 + i) * DD + d]);
#pragma unroll
        for (int m = 0; m < MM; ++m) acc[m] += adjs[m][i] * fe;
    }
    __syncthreads();
    if (half == 1)
#pragma unroll
        for (int m = 0; m < MM; ++m) adjs[m][d] = acc[m];
    __syncthreads();
    if (half == 0)
#pragma unroll
        for (int m = 0; m < MM; ++m)
            atomicAdd(&g_ce[m * DD + d], acc[m] + adjs[m][d]);
}

// ---------------------------------------------------------------------------
// uv: u[c]=ce[c]@W_low, v[p]=ce[p]@W_high; 12 blocks x 512 thr (4 k-chunks)
// ---------------------------------------------------------------------------
__global__ __launch_bounds__(512) void k_uv(const float* __restrict__ wchar) {
    __shared__ float part[4][DD];
    __shared__ float coef[DD];
    const int j  = blockIdx.x;
    const int d  = threadIdx.x & 127;
    const int ch = threadIdx.x >> 7;
    const int src = (j < 2) ? j : (j - 2);
    const int off = (j < 2) ? 0 : DD;

    if (threadIdx.x < DD) coef[threadIdx.x] = g_ce[src * DD + threadIdx.x];
    __syncthreads();

    float s = 0.f;
#pragma unroll 8
    for (int e = ch * 32; e < ch * 32 + 32; ++e)
        s += coef[e] * wchar[(size_t)(off + e) * DD + d];
    part[ch][d] = s;
    __syncthreads();
    if (threadIdx.x < DD)
        g_uv[j * DD + d] = part[0][d] + part[1][d] + part[2][d] + part[3][d];
}

// ---------------------------------------------------------------------------
// lat[combo][d] = sigmoid(u[c][d] + v[p][d])
// ---------------------------------------------------------------------------
__global__ void k_lat_combine() {
    int idx = blockIdx.x * blockDim.x + threadIdx.x;
    if (idx >= 2 * MM * DD) return;
    int combo = idx >> 7, d = idx & 127;
    int cc = combo / MM, p = combo % MM;
    float s = g_uv[cc * DD + d] + g_uv[(2 + p) * DD + d];
    g_lat[idx] = 1.0f / (1.0f + expf(-s));
}

// ---------------------------------------------------------------------------
// attention: flow_all fused on the fly, fp16 gathers, online softmax
// ---------------------------------------------------------------------------
__global__ __launch_bounds__(256) void k_attn(
    const int* __restrict__ history,
    const float* __restrict__ att_w,
    const float* __restrict__ att_b,
    const float* __restrict__ adj)
{
    const int lane = threadIdx.x & 31;
    const int warp = threadIdx.x >> 5;
    const int b = blockIdx.x * 8 + warp;

    const int myn = history[(size_t)b * KK + lane];
    const float4 aw = ((const float4*)att_w)[lane];
    const float ab = att_b[0];
    const float4 c0 = ((const float4*)g_ce)[lane];        // ce row 0
    const float4 c1 = ((const float4*)g_ce)[32 + lane];   // ce row 1

    float m = -INFINITY, l = 0.f;
    float4 acc = make_float4(0.f, 0.f, 0.f, 0.f);

#pragma unroll 4
    for (int k = 0; k < KK; ++k) {
        int n = __shfl_sync(0xFFFFFFFFu, myn, k);
        float a0 = __ldg(&adj[n]);
        float a1 = __ldg(&adj[NN + n]);
        uint2 raw = *(const uint2*)&g_flowh[(size_t)n * DD + lane * 4];
        float2 f0 = __half22float2(*(__half2*)&raw.x);
        float2 f1 = __half22float2(*(__half2*)&raw.y);
        float4 v;
        v.x = 0.5f * (f0.x + a0 * c0.x + a1 * c1.x);
        v.y = 0.5f * (f0.y + a0 * c0.y + a1 * c1.y);
        v.z = 0.5f * (f1.x + a0 * c0.z + a1 * c1.z);
        v.w = 0.5f * (f1.y + a0 * c0.w + a1 * c1.w);

        float p = v.x * aw.x + v.y * aw.y + v.z * aw.z + v.w * aw.w;
#pragma unroll
        for (int off = 16; off > 0; off >>= 1)
            p += __shfl_xor_sync(0xFFFFFFFFu, p, off);
        float s = p + ab;
        float mn = fmaxf(m, s);
        float corr = __expf(m - mn);
        float w = __expf(s - mn);
        l = l * corr + w;
        acc.x = acc.x * corr + w * v.x;
        acc.y = acc.y * corr + w * v.y;
        acc.z = acc.z * corr + w * v.z;
        acc.w = acc.w * corr + w * v.w;
        m = mn;
    }
    float inv = 1.0f / l;
    float4 o = make_float4(acc.x * inv, acc.y * inv, acc.z * inv, acc.w * inv);
    *(float4*)&g_agg[(size_t)b * DD + lane * 4] = o;
}

// ---------------------------------------------------------------------------
// Launch. Inputs:
//  0 feature 1 flow_char_adj 2 history 3 item_id 4 category_r 5 category_n
//  6 PA_level 7 weight_emb 8 bias_emb 9 weight_character 10 att1_w 11 att1_b
// 12 linear1_w 13 linear1_b ; out = [pred_r | pred_n]
// ---------------------------------------------------------------------------
extern "C" void kernel_launch(void* const* d_in, const int* in_sizes, int n_in,
                              void* d_out, int out_size)
{
    const float* feature = (const float*)d_in[0];
    const float* adj     = (const float*)d_in[1];
    const int*   history = (const int*)d_in[2];
    const int*   cat_r   = (const int*)d_in[4];
    const int*   cat_n   = (const int*)d_in[5];
    const int*   pa      = (const int*)d_in[6];
    const float* w_emb   = (const float*)d_in[7];
    const float* b_emb   = (const float*)d_in[8];
    const float* wchar   = (const float*)d_in[9];
    const float* att_w   = (const float*)d_in[10];
    const float* att_b   = (const float*)d_in[11];
    const float* l1w     = (const float*)d_in[12];
    const float* l1b     = (const float*)d_in[13];
    float* out = (float*)d_out;

    float* aggp;  cudaGetSymbolAddress((void**)&aggp,  g_agg);
    float* wsump; cudaGetSymbolAddress((void**)&wsump, g_wsum);

    k_prep<<<256, 256>>>(l1w, out);
    k_gemm<0><<<(NN + 127) / 128, 256>>>(feature, w_emb, b_emb, NN, FF,
                                         nullptr, nullptr, nullptr, nullptr);
    k_spmm<<<(NN + 127) / 128, 256>>>(adj);
    k_uv<<<12, 512>>>(wchar);
    k_lat_combine<<<10, 256>>>();
    k_attn<<<BB / 8, 256>>>(history, att_w, att_b, adj);
    k_gemm<1><<<BB / 128, 256>>>(aggp, wsump, l1b, BB, DD,
                                 cat_r, cat_n, pa, out);
}

// round 9
// speedup vs baseline: 2.4935x; 1.3013x over previous
#include <cuda_runtime.h>
#include <cuda_fp16.h>
#include <math.h>

// Problem constants
#define NN 100000   // nodes
#define FF 256      // feature dim
#define DD 128      // latent dim
#define MM 10       // categories
#define BB 32768    // batch
#define KK 32       // neighbors

// ---------------------------------------------------------------------------
// Scratch
// ---------------------------------------------------------------------------
__device__ __half g_flowh[NN * DD];   // flow_emb fp16, overwritten by flow_all
__device__ float  g_s[NN];            // per-node attention score (pre-softmax)
__device__ float  g_ce[MM * DD];      // character_emb
__device__ float  g_uv[12 * DD];      // u[2][D], v[10][D]
__device__ float  g_lat[2 * MM * DD]; // sigmoid lat table (20 combos)
__device__ float  g_wsum[DD * DD];    // l1w[:D] + l1w[D:]
__device__ float  g_agg[BB * DD];     // attention output

// ---------------------------------------------------------------------------
// bf16 2-way split helpers
// ---------------------------------------------------------------------------
__device__ __forceinline__ unsigned pk2(float lo, float hi) {
    unsigned r;
    asm("cvt.rn.bf16x2.f32 %0, %1, %2;" : "=r"(r) : "f"(hi), "f"(lo));
    return r;
}
__device__ __forceinline__ void cvt_pair(float lo, float hi, unsigned& h, unsigned& l) {
    h = pk2(lo, hi);
    float flo = __uint_as_float(h << 16);
    float fhi = __uint_as_float(h & 0xFFFF0000u);
    l = pk2(lo - flo, hi - fhi);
}
__device__ __forceinline__ void mma_bf16(
    float* c, unsigned a0, unsigned a1, unsigned a2, unsigned a3,
    unsigned b0, unsigned b1)
{
    asm volatile(
        "mma.sync.aligned.m16n8k16.row.col.f32.bf16.bf16.f32 "
        "{%0,%1,%2,%3},{%4,%5,%6,%7},{%8,%9},{%0,%1,%2,%3};"
        : "+f"(c[0]), "+f"(c[1]), "+f"(c[2]), "+f"(c[3])
        : "r"(a0), "r"(a1), "r"(a2), "r"(a3), "r"(b0), "r"(b1));
}

// ---------------------------------------------------------------------------
// bf16-split GEMM: C[M,128] = A[M,K] @ B[K,128] + bias
// BM=128, BN=128, BK=32; 256 threads; warps 4(m)x2(n); warp tile m32 n64.
// A and B both pre-converted to packed bf16 hi/lo planes at staging time;
// mainloop is pure LDS + MMA.
// MODE 0: write C as fp16 to g_flowh.   MODE 1: fused relu+lat-dot epilogue.
// ---------------------------------------------------------------------------
#define A_LD 20      // words per A-plane row (conflict-free: (20*lg+lk)%32 distinct)
#define B_LD 136     // words per B-plane row (136%32=8 -> conflict-free)

template<int MODE>
__global__ __launch_bounds__(256) void k_gemm(
    const float* __restrict__ A,
    const float* __restrict__ B,
    const float* __restrict__ bias,
    int Mrows, int Kdim,
    const int* __restrict__ cat_r,
    const int* __restrict__ cat_n,
    const int* __restrict__ pa,
    float* __restrict__ out)
{
    __shared__ __align__(16) unsigned char smem_raw[37888];
    unsigned* Ah = (unsigned*)smem_raw;                  // 128 x A_LD
    unsigned* Al = (unsigned*)(smem_raw + 10240);        // 128 x A_LD
    unsigned* Bh = (unsigned*)(smem_raw + 20480);        // 16 x B_LD
    unsigned* Bl = (unsigned*)(smem_raw + 29184);        // 16 x B_LD

    const int tid  = threadIdx.x;
    const int lane = tid & 31;
    const int warp = tid >> 5;
    const int wm   = warp >> 1;
    const int wn   = warp & 1;
    const int lg   = lane >> 2;
    const int lk   = lane & 3;
    const int row0 = blockIdx.x * 128;

    float c[2][8][4];
#pragma unroll
    for (int mt = 0; mt < 2; ++mt)
#pragma unroll
        for (int nt = 0; nt < 8; ++nt)
#pragma unroll
            for (int i = 0; i < 4; ++i) c[mt][nt][i] = 0.f;

    const int kt_iters = Kdim >> 5;

    float4 ra[4];
    float4 rb0[2], rb1[2];

    // prefetch tile 0
#pragma unroll
    for (int i = 0; i < 4; ++i) {
        int id = tid + i * 256;
        int r = id >> 3, c4 = id & 7;
        ra[i] = make_float4(0.f, 0.f, 0.f, 0.f);
        if (row0 + r < Mrows)
            ra[i] = *(const float4*)&A[(size_t)(row0 + r) * Kdim + c4 * 4];
    }
#pragma unroll
    for (int i = 0; i < 2; ++i) {
        int id = tid + i * 256;
        int k2 = id >> 5, c4 = id & 31;
        rb0[i] = *(const float4*)&B[(size_t)(2 * k2)     * DD + c4 * 4];
        rb1[i] = *(const float4*)&B[(size_t)(2 * k2 + 1) * DD + c4 * 4];
    }

    for (int kt = 0; kt < kt_iters; ++kt) {
        // --- stage: convert BOTH A and B into packed bf16 hi/lo planes ---
#pragma unroll
        for (int i = 0; i < 4; ++i) {
            int id = tid + i * 256;
            int r = id >> 3, c4 = id & 7;
            unsigned h0, l0, h1, l1;
            cvt_pair(ra[i].x, ra[i].y, h0, l0);
            cvt_pair(ra[i].z, ra[i].w, h1, l1);
            *(uint2*)&Ah[r * A_LD + 2 * c4] = make_uint2(h0, h1);
            *(uint2*)&Al[r * A_LD + 2 * c4] = make_uint2(l0, l1);
        }
#pragma unroll
        for (int i = 0; i < 2; ++i) {
            int id = tid + i * 256;
            int k2 = id >> 5, c4 = id & 31;
            const float* e0 = (const float*)&rb0[i];
            const float* e1 = (const float*)&rb1[i];
            unsigned hj[4], lj[4];
#pragma unroll
            for (int j = 0; j < 4; ++j) cvt_pair(e0[j], e1[j], hj[j], lj[j]);
            *(uint4*)&Bh[k2 * B_LD + c4 * 4] = make_uint4(hj[0], hj[1], hj[2], hj[3]);
            *(uint4*)&Bl[k2 * B_LD + c4 * 4] = make_uint4(lj[0], lj[1], lj[2], lj[3]);
        }
        __syncthreads();

        // --- prefetch next tile ---
        if (kt + 1 < kt_iters) {
            int k0 = (kt + 1) * 32;
#pragma unroll
            for (int i = 0; i < 4; ++i) {
                int id = tid + i * 256;
                int r = id >> 3, c4 = id & 7;
                ra[i] = make_float4(0.f, 0.f, 0.f, 0.f);
                if (row0 + r < Mrows)
                    ra[i] = *(const float4*)&A[(size_t)(row0 + r) * Kdim + k0 + c4 * 4];
            }
#pragma unroll
            for (int i = 0; i < 2; ++i) {
                int id = tid + i * 256;
                int k2 = id >> 5, c4 = id & 31;
                rb0[i] = *(const float4*)&B[(size_t)(k0 + 2 * k2)     * DD + c4 * 4];
                rb1[i] = *(const float4*)&B[(size_t)(k0 + 2 * k2 + 1) * DD + c4 * 4];
            }
        }

        // --- mainloop: pure LDS + MMA ---
#pragma unroll
        for (int s = 0; s < 2; ++s) {
            unsigned ah[2][4], al[2][4];
#pragma unroll
            for (int mt = 0; mt < 2; ++mt) {
                int rb = (wm * 32 + mt * 16 + lg) * A_LD + s * 8 + lk;
                ah[mt][0] = Ah[rb];
                ah[mt][1] = Ah[rb + 8 * A_LD];
                ah[mt][2] = Ah[rb + 4];
                ah[mt][3] = Ah[rb + 8 * A_LD + 4];
                al[mt][0] = Al[rb];
                al[mt][1] = Al[rb + 8 * A_LD];
                al[mt][2] = Al[rb + 4];
                al[mt][3] = Al[rb + 8 * A_LD + 4];
            }
#pragma unroll
            for (int nt = 0; nt < 8; ++nt) {
                int col = wn * 64 + nt * 8 + lg;
                unsigned bh0 = Bh[(s * 8 + lk)     * B_LD + col];
                unsigned bh1 = Bh[(s * 8 + lk + 4) * B_LD + col];
                unsigned bl0 = Bl[(s * 8 + lk)     * B_LD + col];
                unsigned bl1 = Bl[(s * 8 + lk + 4) * B_LD + col];
#pragma unroll
                for (int mt = 0; mt < 2; ++mt) {
                    mma_bf16(c[mt][nt], ah[mt][0], ah[mt][1], ah[mt][2], ah[mt][3], bl0, bl1);
                    mma_bf16(c[mt][nt], al[mt][0], al[mt][1], al[mt][2], al[mt][3], bh0, bh1);
                    mma_bf16(c[mt][nt], ah[mt][0], ah[mt][1], ah[mt][2], ah[mt][3], bh0, bh1);
                }
            }
        }
        __syncthreads();
    }

    if (MODE == 0) {
        __half* Hs = (__half*)smem_raw;   // 128 x 136 halves
#pragma unroll
        for (int mt = 0; mt < 2; ++mt)
#pragma unroll
            for (int nt = 0; nt < 8; ++nt) {
                int r = wm * 32 + mt * 16 + lg;
                int col = wn * 64 + nt * 8 + 2 * lk;
                float bx = bias[col], by = bias[col + 1];
                __half2 v0 = __floats2half2_rn(c[mt][nt][0] + bx, c[mt][nt][1] + by);
                __half2 v1 = __floats2half2_rn(c[mt][nt][2] + bx, c[mt][nt][3] + by);
                *(__half2*)&Hs[r * 136 + col] = v0;
                *(__half2*)&Hs[(r + 8) * 136 + col] = v1;
            }
        __syncthreads();
#pragma unroll
        for (int it = 0; it < 8; ++it) {
            int id = tid + it * 256;
            int r = id >> 4, seg = id & 15;
            if (row0 + r < Mrows)
                *(uint4*)&g_flowh[(size_t)(row0 + r) * DD + seg * 8] =
                    *(const uint4*)&Hs[r * 136 + seg * 8];
        }
    } else {
#pragma unroll
        for (int mt = 0; mt < 2; ++mt)
#pragma unroll
            for (int h = 0; h < 2; ++h) {
                int b = row0 + wm * 32 + mt * 16 + h * 8 + lg;
                int pav = pa[b];
                int ir  = cat_r[b] * MM + pav;
                int in_ = cat_n[b] * MM + pav;
                const float* latr = &g_lat[ir * DD];
                const float* latn = &g_lat[in_ * DD];
                float pr = 0.f, pn = 0.f;
#pragma unroll
                for (int nt = 0; nt < 8; ++nt) {
                    int col = wn * 64 + nt * 8 + 2 * lk;
                    float o0 = fmaxf(c[mt][nt][h * 2 + 0] + bias[col], 0.f);
                    float o1 = fmaxf(c[mt][nt][h * 2 + 1] + bias[col + 1], 0.f);
                    float2 lr = *(const float2*)&latr[col];
                    float2 ln = *(const float2*)&latn[col];
                    pr += o0 * lr.x + o1 * lr.y;
                    pn += o0 * ln.x + o1 * ln.y;
                }
                pr += __shfl_xor_sync(0xFFFFFFFFu, pr, 1);
                pr += __shfl_xor_sync(0xFFFFFFFFu, pr, 2);
                pn += __shfl_xor_sync(0xFFFFFFFFu, pn, 1);
                pn += __shfl_xor_sync(0xFFFFFFFFu, pn, 2);
                if (lk == 0) {
                    atomicAdd(&out[b], pr);
                    atomicAdd(&out[BB + b], pn);
                }
            }
    }
}

// ---------------------------------------------------------------------------
// prep: zero out/ce/uv, compute wsum
// ---------------------------------------------------------------------------
__global__ void k_prep(const float* __restrict__ l1w, float* __restrict__ out) {
    int i = blockIdx.x * blockDim.x + threadIdx.x;
    if (i < 2 * BB) out[i] = 0.f;
    if (i < MM * DD) g_ce[i] = 0.f;
    if (i < 12 * DD) g_uv[i] = 0.f;
    if (i < DD * DD) g_wsum[i] = l1w[i] + l1w[DD * DD + i];
}

// ---------------------------------------------------------------------------
// character_emb = adj @ flow_emb  (reads fp16 flow table, BEFORE flowall)
// ---------------------------------------------------------------------------
__global__ __launch_bounds__(256) void k_spmm(const float* __restrict__ adj) {
    __shared__ float adjs[MM][128];
    const int d    = threadIdx.x & 127;
    const int half = threadIdx.x >> 7;
    const int n0   = blockIdx.x * 128;
    const int cnt  = min(128, NN - n0);

    for (int m = half; m < MM; m += 2)
        adjs[m][d] = (d < cnt) ? adj[(size_t)m * NN + n0 + d] : 0.f;
    __syncthreads();

    float acc[MM];
#pragma unroll
    for (int m = 0; m < MM; ++m) acc[m] = 0.f;

    const int i0 = half * 64, i1 = min(half * 64 + 64, cnt);
#pragma unroll 4
    for (int i = i0; i < i1; ++i) {
        float fe = __half2float(g_flowh[(size_t)(n0 + i) * DD + d]);
#pragma unroll
        for (int m = 0; m < MM; ++m) acc[m] += adjs[m][i] * fe;
    }
    __syncthreads();
    if (half == 1)
#pragma unroll
        for (int m = 0; m < MM; ++m) adjs[m][d] = acc[m];
    __syncthreads();
    if (half == 0)
#pragma unroll
        for (int m = 0; m < MM; ++m)
            atomicAdd(&g_ce[m * DD + d], acc[m] + adjs[m][d]);
}

// ---------------------------------------------------------------------------
// flowall: in-place flow -> flow_all (fp16) + per-node score s[n]
// warp per node
// ---------------------------------------------------------------------------
__global__ __launch_bounds__(256) void k_flowall(
    const float* __restrict__ adj,
    const float* __restrict__ att_w)
{
    const int lane = threadIdx.x & 31;
    const int warp = threadIdx.x >> 5;
    const int n = blockIdx.x * 8 + warp;
    if (n >= NN) return;

    const float4 c0 = ((const float4*)g_ce)[lane];
    const float4 c1 = ((const float4*)g_ce)[32 + lane];
    const float4 aw = ((const float4*)att_w)[lane];
    const float a0 = __ldg(&adj[n]);
    const float a1 = __ldg(&adj[NN + n]);

    uint2 raw = *(const uint2*)&g_flowh[(size_t)n * DD + lane * 4];
    float2 f0 = __half22float2(*(__half2*)&raw.x);
    float2 f1 = __half22float2(*(__half2*)&raw.y);

    float4 v;
    v.x = 0.5f * (f0.x + a0 * c0.x + a1 * c1.x);
    v.y = 0.5f * (f0.y + a0 * c0.y + a1 * c1.y);
    v.z = 0.5f * (f1.x + a0 * c0.z + a1 * c1.z);
    v.w = 0.5f * (f1.y + a0 * c0.w + a1 * c1.w);

    uint2 packed;
    *(__half2*)&packed.x = __floats2half2_rn(v.x, v.y);
    *(__half2*)&packed.y = __floats2half2_rn(v.z, v.w);
    *(uint2*)&g_flowh[(size_t)n * DD + lane * 4] = packed;

    float p = v.x * aw.x + v.y * aw.y + v.z * aw.z + v.w * aw.w;
#pragma unroll
    for (int off = 16; off > 0; off >>= 1)
        p += __shfl_xor_sync(0xFFFFFFFFu, p, off);
    if (lane == 0) g_s[n] = p;
}

// ---------------------------------------------------------------------------
// uv: u/v partials with 4-way k-split, atomicAdd merge. grid (12,4) x 128.
// ---------------------------------------------------------------------------
__global__ __launch_bounds__(128) void k_uv(const float* __restrict__ wchar) {
    const int j  = blockIdx.x;            // 0..11
    const int ch = blockIdx.y;            // 0..3
    const int d  = threadIdx.x;
    const int src = (j < 2) ? j : (j - 2);
    const int off = (j < 2) ? 0 : DD;

    float s = 0.f;
#pragma unroll 8
    for (int e = ch * 32; e < ch * 32 + 32; ++e)
        s += g_ce[src * DD + e] * wchar[(size_t)(off + e) * DD + d];
    atomicAdd(&g_uv[j * DD + d], s);
}

// ---------------------------------------------------------------------------
// lat[combo][d] = sigmoid(u[c][d] + v[p][d])
// ---------------------------------------------------------------------------
__global__ void k_lat_combine() {
    int idx = blockIdx.x * blockDim.x + threadIdx.x;
    if (idx >= 2 * MM * DD) return;
    int combo = idx >> 7, d = idx & 127;
    int cc = combo / MM, p = combo % MM;
    float s = g_uv[cc * DD + d] + g_uv[(2 + p) * DD + d];
    g_lat[idx] = 1.0f / (1.0f + expf(-s));
}

// ---------------------------------------------------------------------------
// attention: weights from precomputed scores, then pure gather+FMA.
// warp per batch row.  (att_b cancels in softmax.)
// ---------------------------------------------------------------------------
__global__ __launch_bounds__(256) void k_attn(const int* __restrict__ history) {
    const int lane = threadIdx.x & 31;
    const int warp = threadIdx.x >> 5;
    const int b = blockIdx.x * 8 + warp;

    const int myn = history[(size_t)b * KK + lane];
    float sc = __ldg(&g_s[myn]);

    float mx = sc;
#pragma unroll
    for (int off = 16; off > 0; off >>= 1)
        mx = fmaxf(mx, __shfl_xor_sync(0xFFFFFFFFu, mx, off));
    float w = __expf(sc - mx);
    float sum = w;
#pragma unroll
    for (int off = 16; off > 0; off >>= 1)
        sum += __shfl_xor_sync(0xFFFFFFFFu, sum, off);
    w *= (1.0f / sum);

    float4 acc = make_float4(0.f, 0.f, 0.f, 0.f);
#pragma unroll
    for (int k = 0; k < KK; ++k) {
        int n = __shfl_sync(0xFFFFFFFFu, myn, k);
        float wk = __shfl_sync(0xFFFFFFFFu, w, k);
        uint2 raw = *(const uint2*)&g_flowh[(size_t)n * DD + lane * 4];
        float2 f0 = __half22float2(*(__half2*)&raw.x);
        float2 f1 = __half22float2(*(__half2*)&raw.y);
        acc.x += wk * f0.x;
        acc.y += wk * f0.y;
        acc.z += wk * f1.x;
        acc.w += wk * f1.y;
    }
    *(float4*)&g_agg[(size_t)b * DD + lane * 4] = acc;
}

// ---------------------------------------------------------------------------
// Launch. Inputs:
//  0 feature 1 flow_char_adj 2 history 3 item_id 4 category_r 5 category_n
//  6 PA_level 7 weight_emb 8 bias_emb 9 weight_character 10 att1_w 11 att1_b
// 12 linear1_w 13 linear1_b ; out = [pred_r | pred_n]
// ---------------------------------------------------------------------------
extern "C" void kernel_launch(void* const* d_in, const int* in_sizes, int n_in,
                              void* d_out, int out_size)
{
    const float* feature = (const float*)d_in[0];
    const float* adj     = (const float*)d_in[1];
    const int*   history = (const int*)d_in[2];
    const int*   cat_r   = (const int*)d_in[4];
    const int*   cat_n   = (const int*)d_in[5];
    const int*   pa      = (const int*)d_in[6];
    const float* w_emb   = (const float*)d_in[7];
    const float* b_emb   = (const float*)d_in[8];
    const float* wchar   = (const float*)d_in[9];
    const float* att_w   = (const float*)d_in[10];
    const float* l1w     = (const float*)d_in[12];
    const float* l1b     = (const float*)d_in[13];
    float* out = (float*)d_out;

    float* aggp;  cudaGetSymbolAddress((void**)&aggp,  g_agg);
    float* wsump; cudaGetSymbolAddress((void**)&wsump, g_wsum);

    k_prep<<<256, 256>>>(l1w, out);
    k_gemm<0><<<(NN + 127) / 128, 256>>>(feature, w_emb, b_emb, NN, FF,
                                         nullptr, nullptr, nullptr, nullptr);
    k_spmm<<<(NN + 127) / 128, 256>>>(adj);
    k_flowall<<<(NN + 7) / 8, 256>>>(adj, att_w);
    k_uv<<<dim3(12, 4), 128>>>(wchar);
    k_lat_combine<<<10, 256>>>();
    k_attn<<<BB / 8, 256>>>(history);
    k_gemm<1><<<BB / 128, 256>>>(aggp, wsump, l1b, BB, DD,
                                 cat_r, cat_n, pa, out);
}

// round 13
// speedup vs baseline: 2.5237x; 1.0121x over previous
#include <cuda_runtime.h>
#include <cuda_fp16.h>
#include <math.h>

// Problem constants
#define NN 100000   // nodes
#define FF 256      // feature dim
#define DD 128      // latent dim
#define MM 10       // categories
#define BB 32768    // batch
#define KK 32       // neighbors

// ---------------------------------------------------------------------------
// Scratch
// ---------------------------------------------------------------------------
__device__ __align__(16) __half g_flowh[NN * DD]; // flow_emb fp16 -> flow_all
__device__ float  g_s[NN];              // per-node attention score
__device__ float  g_ce[MM * DD];        // character_emb
__device__ float  g_uv[12 * DD];        // u[2][D], v[10][D]
__device__ float  g_lat[2 * MM * DD];   // sigmoid lat table
__device__ float  g_wsum[DD * DD];      // l1w[:D] + l1w[D:]
__device__ __align__(16) float g_agg[BB * DD];    // attention output

// ---------------------------------------------------------------------------
// bf16 split helpers
// ---------------------------------------------------------------------------
__device__ __forceinline__ unsigned pk2(float lo, float hi) {
    unsigned r;
    asm("cvt.rn.bf16x2.f32 %0, %1, %2;" : "=r"(r) : "f"(hi), "f"(lo));
    return r;
}
__device__ __forceinline__ void cvt_pair(float lo, float hi, unsigned& h, unsigned& l) {
    h = pk2(lo, hi);
    float flo = __uint_as_float(h << 16);
    float fhi = __uint_as_float(h & 0xFFFF0000u);
    l = pk2(lo - flo, hi - fhi);
}
__device__ __forceinline__ void mma_bf16(
    float* c, unsigned a0, unsigned a1, unsigned a2, unsigned a3,
    unsigned b0, unsigned b1)
{
    asm volatile(
        "mma.sync.aligned.m16n8k16.row.col.f32.bf16.bf16.f32 "
        "{%0,%1,%2,%3},{%4,%5,%6,%7},{%8,%9},{%0,%1,%2,%3};"
        : "+f"(c[0]), "+f"(c[1]), "+f"(c[2]), "+f"(c[3])
        : "r"(a0), "r"(a1), "r"(a2), "r"(a3), "r"(b0), "r"(b1));
}

// ---------------------------------------------------------------------------
// bf16-split GEMM: C[M,128] = A[M,K] @ B[K,128] + bias
// BM=128, BN=128, BK=32; 256 threads; warps 4(m)x2(n); warp tile m32 n64.
// A and B pre-converted to packed bf16 hi/lo planes at staging; mainloop is
// pure LDS + MMA (mma.sync m16n8k16, compute_103-safe).
// MODE 0: write C as fp16 to g_flowh.   MODE 1: fused relu+lat-dot epilogue.
// ---------------------------------------------------------------------------
#define A_LD 20      // words per A-plane row
#define B_LD 136     // words per B-plane row

template<int MODE>
__global__ __launch_bounds__(256) void k_gemm(
    const float* __restrict__ A,
    const float* __restrict__ B,
    const float* __restrict__ bias,
    int Mrows, int Kdim,
    const int* __restrict__ cat_r,
    const int* __restrict__ cat_n,
    const int* __restrict__ pa,
    float* __restrict__ out)
{
    __shared__ __align__(16) unsigned char smem_raw[37888];
    unsigned* Ah = (unsigned*)smem_raw;                  // 128 x A_LD
    unsigned* Al = (unsigned*)(smem_raw + 10240);        // 128 x A_LD
    unsigned* Bh = (unsigned*)(smem_raw + 20480);        // 16 x B_LD
    unsigned* Bl = (unsigned*)(smem_raw + 29184);        // 16 x B_LD

    const int tid  = threadIdx.x;
    const int lane = tid & 31;
    const int warp = tid >> 5;
    const int wm   = warp >> 1;
    const int wn   = warp & 1;
    const int lg   = lane >> 2;
    const int lk   = lane & 3;
    const int row0 = blockIdx.x * 128;

    float c[2][8][4];
#pragma unroll
    for (int mt = 0; mt < 2; ++mt)
#pragma unroll
        for (int nt = 0; nt < 8; ++nt)
#pragma unroll
            for (int i = 0; i < 4; ++i) c[mt][nt][i] = 0.f;

    const int kt_iters = Kdim >> 5;
    float4 ra[4];
    float4 rb0[2], rb1[2];

    // prefetch tile 0
#pragma unroll
    for (int i = 0; i < 4; ++i) {
        int id = tid + i * 256;
        int r = id >> 3, c4 = id & 7;
        ra[i] = make_float4(0.f, 0.f, 0.f, 0.f);
        if (row0 + r < Mrows)
            ra[i] = *(const float4*)&A[(size_t)(row0 + r) * Kdim + c4 * 4];
    }
#pragma unroll
    for (int i = 0; i < 2; ++i) {
        int id = tid + i * 256;
        int k2 = id >> 5, c4 = id & 31;
        rb0[i] = *(const float4*)&B[(size_t)(2 * k2)     * DD + c4 * 4];
        rb1[i] = *(const float4*)&B[(size_t)(2 * k2 + 1) * DD + c4 * 4];
    }

    for (int kt = 0; kt < kt_iters; ++kt) {
        // stage: convert BOTH A and B into packed bf16 hi/lo planes
#pragma unroll
        for (int i = 0; i < 4; ++i) {
            int id = tid + i * 256;
            int r = id >> 3, c4 = id & 7;
            unsigned h0, l0, h1, l1;
            cvt_pair(ra[i].x, ra[i].y, h0, l0);
            cvt_pair(ra[i].z, ra[i].w, h1, l1);
            *(uint2*)&Ah[r * A_LD + 2 * c4] = make_uint2(h0, h1);
            *(uint2*)&Al[r * A_LD + 2 * c4] = make_uint2(l0, l1);
        }
#pragma unroll
        for (int i = 0; i < 2; ++i) {
            int id = tid + i * 256;
            int k2 = id >> 5, c4 = id & 31;
            const float* e0 = (const float*)&rb0[i];
            const float* e1 = (const float*)&rb1[i];
            unsigned hj[4], lj[4];
#pragma unroll
            for (int j = 0; j < 4; ++j) cvt_pair(e0[j], e1[j], hj[j], lj[j]);
            *(uint4*)&Bh[k2 * B_LD + c4 * 4] = make_uint4(hj[0], hj[1], hj[2], hj[3]);
            *(uint4*)&Bl[k2 * B_LD + c4 * 4] = make_uint4(lj[0], lj[1], lj[2], lj[3]);
        }
        __syncthreads();

        // prefetch next tile
        if (kt + 1 < kt_iters) {
            int k0 = (kt + 1) * 32;
#pragma unroll
            for (int i = 0; i < 4; ++i) {
                int id = tid + i * 256;
                int r = id >> 3, c4 = id & 7;
                ra[i] = make_float4(0.f, 0.f, 0.f, 0.f);
                if (row0 + r < Mrows)
                    ra[i] = *(const float4*)&A[(size_t)(row0 + r) * Kdim + k0 + c4 * 4];
            }
#pragma unroll
            for (int i = 0; i < 2; ++i) {
                int id = tid + i * 256;
                int k2 = id >> 5, c4 = id & 31;
                rb0[i] = *(const float4*)&B[(size_t)(k0 + 2 * k2)     * DD + c4 * 4];
                rb1[i] = *(const float4*)&B[(size_t)(k0 + 2 * k2 + 1) * DD + c4 * 4];
            }
        }

        // mainloop: pure LDS + MMA
#pragma unroll
        for (int s = 0; s < 2; ++s) {
            unsigned ah[2][4], al[2][4];
#pragma unroll
            for (int mt = 0; mt < 2; ++mt) {
                int rb = (wm * 32 + mt * 16 + lg) * A_LD + s * 8 + lk;
                ah[mt][0] = Ah[rb];
                ah[mt][1] = Ah[rb + 8 * A_LD];
                ah[mt][2] = Ah[rb + 4];
                ah[mt][3] = Ah[rb + 8 * A_LD + 4];
                al[mt][0] = Al[rb];
                al[mt][1] = Al[rb + 8 * A_LD];
                al[mt][2] = Al[rb + 4];
                al[mt][3] = Al[rb + 8 * A_LD + 4];
            }
#pragma unroll
            for (int nt = 0; nt < 8; ++nt) {
                int col = wn * 64 + nt * 8 + lg;
                unsigned bh0 = Bh[(s * 8 + lk)     * B_LD + col];
                unsigned bh1 = Bh[(s * 8 + lk + 4) * B_LD + col];
                unsigned bl0 = Bl[(s * 8 + lk)     * B_LD + col];
                unsigned bl1 = Bl[(s * 8 + lk + 4) * B_LD + col];
#pragma unroll
                for (int mt = 0; mt < 2; ++mt) {
                    mma_bf16(c[mt][nt], ah[mt][0], ah[mt][1], ah[mt][2], ah[mt][3], bl0, bl1);
                    mma_bf16(c[mt][nt], al[mt][0], al[mt][1], al[mt][2], al[mt][3], bh0, bh1);
                    mma_bf16(c[mt][nt], ah[mt][0], ah[mt][1], ah[mt][2], ah[mt][3], bh0, bh1);
                }
            }
        }
        __syncthreads();
    }

    if (MODE == 0) {
        __half* Hs = (__half*)smem_raw;   // 128 x 136 halves
#pragma unroll
        for (int mt = 0; mt < 2; ++mt)
#pragma unroll
            for (int nt = 0; nt < 8; ++nt) {
                int r = wm * 32 + mt * 16 + lg;
                int col = wn * 64 + nt * 8 + 2 * lk;
                float bx = bias[col], by = bias[col + 1];
                __half2 v0 = __floats2half2_rn(c[mt][nt][0] + bx, c[mt][nt][1] + by);
                __half2 v1 = __floats2half2_rn(c[mt][nt][2] + bx, c[mt][nt][3] + by);
                *(__half2*)&Hs[r * 136 + col] = v0;
                *(__half2*)&Hs[(r + 8) * 136 + col] = v1;
            }
        __syncthreads();
#pragma unroll
        for (int it = 0; it < 8; ++it) {
            int id = tid + it * 256;
            int r = id >> 4, seg = id & 15;
            if (row0 + r < Mrows)
                *(uint4*)&g_flowh[(size_t)(row0 + r) * DD + seg * 8] =
                    *(const uint4*)&Hs[r * 136 + seg * 8];
        }
    } else {
#pragma unroll
        for (int mt = 0; mt < 2; ++mt)
#pragma unroll
            for (int h = 0; h < 2; ++h) {
                int b = row0 + wm * 32 + mt * 16 + h * 8 + lg;
                int pav = pa[b];
                int ir  = cat_r[b] * MM + pav;
                int in_ = cat_n[b] * MM + pav;
                const float* latr = &g_lat[ir * DD];
                const float* latn = &g_lat[in_ * DD];
                float pr = 0.f, pn = 0.f;
#pragma unroll
                for (int nt = 0; nt < 8; ++nt) {
                    int col = wn * 64 + nt * 8 + 2 * lk;
                    float o0 = fmaxf(c[mt][nt][h * 2 + 0] + bias[col], 0.f);
                    float o1 = fmaxf(c[mt][nt][h * 2 + 1] + bias[col + 1], 0.f);
                    float2 lr = *(const float2*)&latr[col];
                    float2 ln = *(const float2*)&latn[col];
                    pr += o0 * lr.x + o1 * lr.y;
                    pn += o0 * ln.x + o1 * ln.y;
                }
                pr += __shfl_xor_sync(0xFFFFFFFFu, pr, 1);
                pr += __shfl_xor_sync(0xFFFFFFFFu, pr, 2);
                pn += __shfl_xor_sync(0xFFFFFFFFu, pn, 1);
                pn += __shfl_xor_sync(0xFFFFFFFFu, pn, 2);
                if (lk == 0) {
                    atomicAdd(&out[b], pr);
                    atomicAdd(&out[BB + b], pn);
                }
            }
    }
}

// ---------------------------------------------------------------------------
// prep: zero out/ce/uv, wsum
// ---------------------------------------------------------------------------
__global__ void k_prep(const float* __restrict__ l1w, float* __restrict__ out) {
    int i = blockIdx.x * blockDim.x + threadIdx.x;
    if (i < 2 * BB) out[i] = 0.f;
    if (i < MM * DD) g_ce[i] = 0.f;
    if (i < 12 * DD) g_uv[i] = 0.f;
    if (i < DD * DD) g_wsum[i] = l1w[i] + l1w[DD * DD + i];
}

// ---------------------------------------------------------------------------
// spmm: ce = adj @ flow_emb (half2 loads, 4-way node split)
// ---------------------------------------------------------------------------
__global__ __launch_bounds__(256) void k_spmm(const float* __restrict__ adj) {
    __shared__ float adjs[MM][128];
    __shared__ float part[4][MM][128];
    const int tid = threadIdx.x;
    const int d2  = tid & 63;       // dim pair
    const int q   = tid >> 6;       // node quarter
    const int n0  = blockIdx.x * 128;

    for (int j = tid; j < MM * 128; j += 256) {
        int m = j >> 7, ii = j & 127;
        adjs[m][ii] = (n0 + ii < NN) ? adj[(size_t)m * NN + n0 + ii] : 0.f;
    }
    __syncthreads();

    float2 acc[MM];
#pragma unroll
    for (int m = 0; m < MM; ++m) acc[m] = make_float2(0.f, 0.f);

    const int iend = min(q * 32 + 32, max(0, NN - n0));
#pragma unroll 4
    for (int i = q * 32; i < iend; ++i) {
        __half2 hv = *(const __half2*)&g_flowh[(size_t)(n0 + i) * DD + d2 * 2];
        float2 f = __half22float2(hv);
#pragma unroll
        for (int m = 0; m < MM; ++m) {
            acc[m].x += adjs[m][i] * f.x;
            acc[m].y += adjs[m][i] * f.y;
        }
    }
#pragma unroll
    for (int m = 0; m < MM; ++m)
        *(float2*)&part[q][m][d2 * 2] = acc[m];
    __syncthreads();

    for (int j = tid; j < MM * 128; j += 256) {
        int m = j >> 7, d = j & 127;
        float s = part[0][m][d] + part[1][m][d] + part[2][m][d] + part[3][m][d];
        atomicAdd(&g_ce[m * DD + d], s);
    }
}

// ---------------------------------------------------------------------------
// flowall: half-warp per node, uint4 access; writes flow_all fp16 + score
// ---------------------------------------------------------------------------
__global__ __launch_bounds__(256) void k_flowall(
    const float* __restrict__ adj,
    const float* __restrict__ att_w)
{
    const int lane = threadIdx.x & 31;
    const int warp = threadIdx.x >> 5;
    const int g  = lane >> 4;
    const int hl = lane & 15;
    const int n = blockIdx.x * 16 + warp * 2 + g;
    if (n >= NN) return;

    const float4 c0a = *(const float4*)&g_ce[hl * 8];
    const float4 c0b = *(const float4*)&g_ce[hl * 8 + 4];
    const float4 c1a = *(const float4*)&g_ce[DD + hl * 8];
    const float4 c1b = *(const float4*)&g_ce[DD + hl * 8 + 4];
    const float4 awa = *(const float4*)&att_w[hl * 8];
    const float4 awb = *(const float4*)&att_w[hl * 8 + 4];
    const float a0 = __ldg(&adj[n]);
    const float a1 = __ldg(&adj[NN + n]);

    uint4 raw = *(const uint4*)&g_flowh[(size_t)n * DD + hl * 8];
    float2 f0 = __half22float2(*(__half2*)&raw.x);
    float2 f1 = __half22float2(*(__half2*)&raw.y);
    float2 f2 = __half22float2(*(__half2*)&raw.z);
    float2 f3 = __half22float2(*(__half2*)&raw.w);

    float v0 = 0.5f * (f0.x + a0 * c0a.x + a1 * c1a.x);
    float v1 = 0.5f * (f0.y + a0 * c0a.y + a1 * c1a.y);
    float v2 = 0.5f * (f1.x + a0 * c0a.z + a1 * c1a.z);
    float v3 = 0.5f * (f1.y + a0 * c0a.w + a1 * c1a.w);
    float v4 = 0.5f * (f2.x + a0 * c0b.x + a1 * c1b.x);
    float v5 = 0.5f * (f2.y + a0 * c0b.y + a1 * c1b.y);
    float v6 = 0.5f * (f3.x + a0 * c0b.z + a1 * c1b.z);
    float v7 = 0.5f * (f3.y + a0 * c0b.w + a1 * c1b.w);

    uint4 pkd;
    __half2 t;
    t = __floats2half2_rn(v0, v1); pkd.x = *(unsigned*)&t;
    t = __floats2half2_rn(v2, v3); pkd.y = *(unsigned*)&t;
    t = __floats2half2_rn(v4, v5); pkd.z = *(unsigned*)&t;
    t = __floats2half2_rn(v6, v7); pkd.w = *(unsigned*)&t;
    *(uint4*)&g_flowh[(size_t)n * DD + hl * 8] = pkd;

    float p = v0 * awa.x + v1 * awa.y + v2 * awa.z + v3 * awa.w
            + v4 * awb.x + v5 * awb.y + v6 * awb.z + v7 * awb.w;
#pragma unroll
    for (int off = 8; off > 0; off >>= 1)
        p += __shfl_xor_sync(0xFFFFFFFFu, p, off);
    if (hl == 0) g_s[n] = p;
}

// ---------------------------------------------------------------------------
// uv: 4-way k-split partials, atomicAdd merge
// ---------------------------------------------------------------------------
__global__ __launch_bounds__(128) void k_uv(const float* __restrict__ wchar) {
    const int j  = blockIdx.x;
    const int ch = blockIdx.y;
    const int d  = threadIdx.x;
    const int src = (j < 2) ? j : (j - 2);
    const int off = (j < 2) ? 0 : DD;

    float s = 0.f;
#pragma unroll 8
    for (int e = ch * 32; e < ch * 32 + 32; ++e)
        s += g_ce[src * DD + e] * wchar[(size_t)(off + e) * DD + d];
    atomicAdd(&g_uv[j * DD + d], s);
}

__global__ void k_lat_combine() {
    int idx = blockIdx.x * blockDim.x + threadIdx.x;
    if (idx >= 2 * MM * DD) return;
    int combo = idx >> 7, d = idx & 127;
    int cc = combo / MM, p = combo % MM;
    float s = g_uv[cc * DD + d] + g_uv[(2 + p) * DD + d];
    g_lat[idx] = 1.0f / (1.0f + expf(-s));
}

// ---------------------------------------------------------------------------
// attention: softmax from precomputed scores, uint4 gathers (half-warp)
// ---------------------------------------------------------------------------
__global__ __launch_bounds__(256) void k_attn(const int* __restrict__ history) {
    const int lane = threadIdx.x & 31;
    const int warp = threadIdx.x >> 5;
    const int b = blockIdx.x * 8 + warp;
    const int g  = lane >> 4;
    const int hl = lane & 15;

    const int myn = history[(size_t)b * KK + lane];
    float sc = __ldg(&g_s[myn]);

    float mx = sc;
#pragma unroll
    for (int off = 16; off > 0; off >>= 1)
        mx = fmaxf(mx, __shfl_xor_sync(0xFFFFFFFFu, mx, off));
    float w = __expf(sc - mx);
    float sum = w;
#pragma unroll
    for (int off = 16; off > 0; off >>= 1)
        sum += __shfl_xor_sync(0xFFFFFFFFu, sum, off);
    w *= (1.0f / sum);

    float a0 = 0.f, a1 = 0.f, a2 = 0.f, a3 = 0.f,
          a4 = 0.f, a5 = 0.f, a6 = 0.f, a7 = 0.f;
#pragma unroll
    for (int k = 0; k < 16; ++k) {
        int idx = 2 * k + g;
        int n = __shfl_sync(0xFFFFFFFFu, myn, idx);
        float wk = __shfl_sync(0xFFFFFFFFu, w, idx);
        uint4 raw = *(const uint4*)&g_flowh[(size_t)n * DD + hl * 8];
        float2 f0 = __half22float2(*(__half2*)&raw.x);
        float2 f1 = __half22float2(*(__half2*)&raw.y);
        float2 f2 = __half22float2(*(__half2*)&raw.z);
        float2 f3 = __half22float2(*(__half2*)&raw.w);
        a0 += wk * f0.x; a1 += wk * f0.y;
        a2 += wk * f1.x; a3 += wk * f1.y;
        a4 += wk * f2.x; a5 += wk * f2.y;
        a6 += wk * f3.x; a7 += wk * f3.y;
    }
    a0 += __shfl_xor_sync(0xFFFFFFFFu, a0, 16);
    a1 += __shfl_xor_sync(0xFFFFFFFFu, a1, 16);
    a2 += __shfl_xor_sync(0xFFFFFFFFu, a2, 16);
    a3 += __shfl_xor_sync(0xFFFFFFFFu, a3, 16);
    a4 += __shfl_xor_sync(0xFFFFFFFFu, a4, 16);
    a5 += __shfl_xor_sync(0xFFFFFFFFu, a5, 16);
    a6 += __shfl_xor_sync(0xFFFFFFFFu, a6, 16);
    a7 += __shfl_xor_sync(0xFFFFFFFFu, a7, 16);
    if (g == 0) {
        *(float4*)&g_agg[(size_t)b * DD + hl * 8]     = make_float4(a0, a1, a2, a3);
        *(float4*)&g_agg[(size_t)b * DD + hl * 8 + 4] = make_float4(a4, a5, a6, a7);
    }
}

// ---------------------------------------------------------------------------
// Launch. Inputs:
//  0 feature 1 flow_char_adj 2 history 3 item_id 4 category_r 5 category_n
//  6 PA_level 7 weight_emb 8 bias_emb 9 weight_character 10 att1_w 11 att1_b
// 12 linear1_w 13 linear1_b ; out = [pred_r | pred_n]
// ---------------------------------------------------------------------------
extern "C" void kernel_launch(void* const* d_in, const int* in_sizes, int n_in,
                              void* d_out, int out_size)
{
    const float* feature = (const float*)d_in[0];
    const float* adj     = (const float*)d_in[1];
    const int*   history = (const int*)d_in[2];
    const int*   cat_r   = (const int*)d_in[4];
    const int*   cat_n   = (const int*)d_in[5];
    const int*   pa      = (const int*)d_in[6];
    const float* w_emb   = (const float*)d_in[7];
    const float* b_emb   = (const float*)d_in[8];
    const float* wchar   = (const float*)d_in[9];
    const float* att_w   = (const float*)d_in[10];
    const float* l1w     = (const float*)d_in[12];
    const float* l1b     = (const float*)d_in[13];
    float* out = (float*)d_out;

    float* aggp;  cudaGetSymbolAddress((void**)&aggp,  g_agg);
    float* wsump; cudaGetSymbolAddress((void**)&wsump, g_wsum);

    k_prep<<<256, 256>>>(l1w, out);
    k_gemm<0><<<(NN + 127) / 128, 256>>>(feature, w_emb, b_emb, NN, FF,
                                         nullptr, nullptr, nullptr, nullptr);
    k_spmm<<<(NN + 127) / 128, 256>>>(adj);
    k_flowall<<<(NN + 15) / 16, 256>>>(adj, att_w);
    k_uv<<<dim3(12, 4), 128>>>(wchar);
    k_lat_combine<<<10, 256>>>();
    k_attn<<<BB / 8, 256>>>(history);
    k_gemm<1><<<BB / 128, 256>>>(aggp, wsump, l1b, BB, DD,
                                 cat_r, cat_n, pa, out);
}